// round 15
// baseline (speedup 1.0000x reference)
#include <cuda_runtime.h>

#define BATCH 128
#define HH 19
#define AA 5
#define CC 81
#define NN 361
#define NAA 1805
#define MM 24
#define ROWS 231040          // BATCH*NAA
#define NBOX (BATCH*MM)      // 3072
#define EPSF 1e-7f

#define NBLK 740             // 148 SMs * 5 blocks
#define NTHR 128             // 4 warps per block -> 10.4KB smem per warp
#define NWPB (NTHR/32)       // 4
#define WROWS 4              // rows per tile
#define WELEM (WROWS*CC)     // 324 floats = 1296 B (16B-divisible)
#define WF4   (WELEM/4)      // 81
#define DEPTH 8              // ring depth: 7 tiles (9KB) in flight per warp
#define NWT   (ROWS/WROWS)   // 57760 tiles
#define TOTW  (NBLK*NWPB)    // 2960 warps
#define KBASE (NWT/TOTW)     // 19
#define KREM  (NWT%TOTW)     // 1520 warps get 20 tiles

// ---- device scratch (zero-init; reset by finishing block each call) ----
__device__ float g_Sce[NAA];
__device__ float g_cnt[NAA];
__device__ float g_corr[NAA];
__device__ float g_acc[8];        // 0 noobj_sub, 1 obj, 2 xy, 3 wh, 4 noobj_total
__device__ unsigned g_done;

__constant__ float c_aw[5] = {0.57273f, 1.87446f, 3.33843f, 7.88282f, 9.77052f};
__constant__ float c_ah[5] = {0.677385f, 2.06253f, 5.47434f, 3.52778f, 9.16828f};

__device__ __forceinline__ void cp16(unsigned s, const void* g) {
    asm volatile("cp.async.cg.shared.global [%0], [%1], 16;\n" :: "r"(s), "l"(g));
}
__device__ __forceinline__ void cpcommit() {
    asm volatile("cp.async.commit_group;\n" ::: "memory");
}
__device__ __forceinline__ void issue_tile(unsigned dstb, const float* cls, int t, int lane) {
    const char* src = (const char*)(cls + (size_t)t * WELEM);
    #pragma unroll
    for (int i = lane; i < WF4; i += 32)
        cp16(dstb + i * 16, src + (size_t)i * 16);
    cpcommit();
}

__global__ void __launch_bounds__(NTHR, 5)
yolo_loss_kernel(const float* __restrict__ conf,
                 const float* __restrict__ pred_xy,
                 const float* __restrict__ pred_wh,
                 const float* __restrict__ cls,
                 const float* __restrict__ tlabel,
                 const float* __restrict__ tobj,
                 float* __restrict__ out, int out_size) {
    __shared__ __align__(16) float sm[NWPB][DEPTH][WELEM];   // 41472 B
    __shared__ float s_no[NWPB];
    __shared__ int   s_last;

    const int tid  = threadIdx.x;
    const int lane = tid & 31;
    const int wid  = tid >> 5;
    const int bx   = blockIdx.x;

    // ====== per-warp run assignment (contiguous 19-20 tiles = ~25KB) ======
    const int gw = bx * NWPB + wid;                           // 0..2959
    const int tbase = (gw < KREM) ? gw * (KBASE + 1)
                                  : KREM * (KBASE + 1) + (gw - KREM) * KBASE;
    const int tcnt  = (gw < KREM) ? (KBASE + 1) : KBASE;      // 20 or 19

    unsigned smb[DEPTH];
    #pragma unroll
    for (int d = 0; d < DEPTH; d++)
        smb[d] = (unsigned)__cvta_generic_to_shared(&sm[wid][d][0]);

    // ====== prologue: fill the ring with 7 tiles (tcnt >= 19 always) ======
    #pragma unroll
    for (int d = 0; d < DEPTH - 1; d++)
        issue_tile(smb[d], cls, tbase + d, lane);

    // ====== Phase 1: gt assignment, 1-2 boxes per warp, lane-parallel ======
    for (int bb = gw; bb < NBOX; bb += TOTW) {
        const float4 tov = *(const float4*)(tobj + (size_t)bb * 4);
        float gx = tov.x * (1.f/32.f), gy = tov.y * (1.f/32.f);
        float gwd = tov.z * (1.f/32.f), ghd = tov.w * (1.f/32.f);
        int cell = (int)gy * HH + (int)gx;
        int b = bb / MM;
        int base = (b * NN + cell) * AA;

        float bi = -1.f; int best = 0; unsigned overm = 0;
        #pragma unroll
        for (int a = 0; a < 5; a++) {
            float inter = fminf(c_aw[a], gwd) * fminf(c_ah[a], ghd);
            float iou = inter / (c_aw[a] * c_ah[a] + gwd * ghd - inter + EPSF);
            if (iou > 0.6f) overm |= (1u << a);
            if (iou > bi) { bi = iou; best = a; }
        }

        const float* tl = tlabel + (size_t)bb * CC;
        unsigned m0 = __ballot_sync(0xffffffffu, tl[lane] > 0.5f);
        unsigned m1 = __ballot_sync(0xffffffffu, tl[lane + 32] > 0.5f);
        unsigned m2 = __ballot_sync(0xffffffffu, (lane < CC - 64) && (tl[lane + 64] > 0.5f));
        int lab = CC - 1;
        if (m0)      lab = __ffs(m0) - 1;
        else if (m1) lab = 32 + __ffs(m1) - 1;
        else if (m2) lab = 64 + __ffs(m2) - 1;

        if (lane < 5) {
            const int a = lane;
            const bool act = (a == best) || ((overm >> a) & 1u);
            if (act) {
                float ca = fminf(fmaxf(conf[base + a], EPSF), 1.f - EPSF);
                atomicAdd(&g_acc[0], -__logf(1.f - ca));
                const float* crow = cls + (size_t)(base + a) * CC;
                atomicAdd(&g_corr[cell * AA + a], crow[CC - 1] - crow[lab]);
            }
            if (a == best) {
                float pw = pred_wh[(size_t)(base + a) * 2];
                float ph = pred_wh[(size_t)(base + a) * 2 + 1];
                float inter = fminf(pw, gwd) * fminf(ph, ghd);
                float iou_pg = inter / (pw * ph + gwd * ghd - inter + EPSF);
                float sw = 2.f - (gwd * (1.f/19.f)) * (ghd * (1.f/19.f));
                float cp = fminf(fmaxf(conf[base + a], EPSF), 1.f - EPSF);
                float objc = -(iou_pg * __logf(cp) + (1.f - iou_pg) * __logf(1.f - cp));
                float px = pred_xy[(size_t)(base + a) * 2];
                float py = pred_xy[(size_t)(base + a) * 2 + 1];
                float xyc = sw * ((px - gx) * (px - gx) + (py - gy) * (py - gy));
                float whc = sw * ((pw - gwd) * (pw - gwd) + (ph - ghd) * (ph - ghd));
                atomicAdd(&g_cnt[cell * AA + a], 1.f);
                atomicAdd(&g_acc[1], objc);
                atomicAdd(&g_acc[2], xyc);
                atomicAdd(&g_acc[3], whc);
            }
        }
    }

    // ====== conf noobj pass (overlaps in-flight copies) ======
    float nacc = 0.f;
    {
        const float4* c4 = (const float4*)conf;
        for (int i = bx * NTHR + tid; i < ROWS / 4; i += NBLK * NTHR) {
            float4 v = c4[i];
            float p0 = fminf(fmaxf(v.x, EPSF), 1.f - EPSF);
            float p1 = fminf(fmaxf(v.y, EPSF), 1.f - EPSF);
            float p2 = fminf(fmaxf(v.z, EPSF), 1.f - EPSF);
            float p3 = fminf(fmaxf(v.w, EPSF), 1.f - EPSF);
            nacc -= __logf(1.f - p0) + __logf(1.f - p1)
                  + __logf(1.f - p2) + __logf(1.f - p3);
        }
    }

    // ====== Phase 2: depth-8 ring over contiguous run ======
    const int r = lane >> 3;              // 0..3 (row within tile)
    const int q = lane & 7;               // 8 lanes per row
    const int start = (q == 0) ? 0 : (10 * q + 1);    // 0,11,21,...,71

    int n0 = (tbase * WROWS) % NAA;       // row index mod NAA; +4 per tile
    int j = 0;

    // main loop: always 7 tiles ahead
    for (; j + (DEPTH - 1) < tcnt; j++) {
        issue_tile(smb[(j + DEPTH - 1) & (DEPTH - 1)], cls, tbase + j + DEPTH - 1, lane);
        asm volatile("cp.async.wait_group %0;\n" :: "n"(DEPTH - 1) : "memory");
        __syncwarp();
        {
            const float* rp = &sm[wid][j & (DEPTH - 1)][r * CC + start];
            float a0 = 0.f, a1 = 0.f;
            #pragma unroll
            for (int i = 0; i < 10; i += 2) {
                a0 += __expf(rp[i]);
                a1 += __expf(rp[i + 1]);
            }
            float x80 = rp[9];                     // q==7: 71+9 = 80
            if (q == 0) a0 += __expf(rp[10]);
            float s = a0 + a1;
            s += __shfl_xor_sync(0xffffffffu, s, 1);
            s += __shfl_xor_sync(0xffffffffu, s, 2);
            s += __shfl_xor_sync(0xffffffffu, s, 4);
            if (q == 7) {
                int idx = n0 + r;
                if (idx >= NAA) idx -= NAA;
                atomicAdd(&g_Sce[idx], __logf(s) - x80);
            }
        }
        __syncwarp();                     // before next issue overwrites slot j&7
        n0 += WROWS;
        if (n0 >= NAA) n0 -= NAA;
    }

    // epilogue: all remaining tiles already issued; drain once, compute barrier-free
    asm volatile("cp.async.wait_group 0;\n" ::: "memory");
    __syncwarp();
    for (; j < tcnt; j++) {
        const float* rp = &sm[wid][j & (DEPTH - 1)][r * CC + start];
        float a0 = 0.f, a1 = 0.f;
        #pragma unroll
        for (int i = 0; i < 10; i += 2) {
            a0 += __expf(rp[i]);
            a1 += __expf(rp[i + 1]);
        }
        float x80 = rp[9];
        if (q == 0) a0 += __expf(rp[10]);
        float s = a0 + a1;
        s += __shfl_xor_sync(0xffffffffu, s, 1);
        s += __shfl_xor_sync(0xffffffffu, s, 2);
        s += __shfl_xor_sync(0xffffffffu, s, 4);
        if (q == 7) {
            int idx = n0 + r;
            if (idx >= NAA) idx -= NAA;
            atomicAdd(&g_Sce[idx], __logf(s) - x80);
        }
        n0 += WROWS;
        if (n0 >= NAA) n0 -= NAA;
    }

    // ====== block-reduce noobj partial, then last-block combine ======
    #pragma unroll
    for (int o = 16; o > 0; o >>= 1)
        nacc += __shfl_xor_sync(0xffffffffu, nacc, o);
    if (lane == 0) s_no[wid] = nacc;
    __syncthreads();
    if (tid == 0) {
        float tn = 0.f;
        #pragma unroll
        for (int i = 0; i < NWPB; i++) tn += s_no[i];
        atomicAdd(&g_acc[4], tn);
        __threadfence();
        unsigned d = atomicAdd(&g_done, 1u);
        s_last = (d == (unsigned)(gridDim.x - 1)) ? 1 : 0;
    }
    __syncthreads();

    if (s_last) {
        __threadfence();
        float* red = &sm[0][0][0];
        float p = 0.f;
        for (int n = tid; n < NAA; n += NTHR)
            p += g_cnt[n] * (g_Sce[n] + g_corr[n]);
        red[tid] = p;
        __syncthreads();
        for (int s2 = NTHR / 2; s2 > 0; s2 >>= 1) {
            if (tid < s2) red[tid] += red[tid + s2];
            __syncthreads();
        }
        if (tid == 0) {
            const float invB = 1.f / (float)BATCH;
            float noobj = (g_acc[4] - g_acc[0]) * invB;   // SCALE_NOOBJ = 1
            float obj   = 5.f * g_acc[1] * invB;
            float xy    = 5.f * g_acc[2] * invB;
            float wh    = 5.f * g_acc[3] * invB;
            float score = 5.f * red[0] * invB;
            float total = noobj + obj + xy + wh + score;
            out[0] = total;
            if (out_size >= 6) {
                out[1] = noobj; out[2] = obj; out[3] = score; out[4] = xy; out[5] = wh;
            }
        }
        __syncthreads();
        for (int n = tid; n < NAA; n += NTHR) {
            g_Sce[n] = 0.f; g_cnt[n] = 0.f; g_corr[n] = 0.f;
        }
        if (tid < 8) g_acc[tid] = 0.f;
        if (tid == 0) g_done = 0u;
        __threadfence();
    }
}

extern "C" void kernel_launch(void* const* d_in, const int* in_sizes, int n_in,
                              void* d_out, int out_size) {
    const float *conf = nullptr, *pxy = nullptr, *pwh = nullptr;
    const float *cls = nullptr, *tl = nullptr, *tobj = nullptr;
    for (int i = 0; i < n_in; i++) {
        int s = in_sizes[i];
        if (s == ROWS)                   conf = (const float*)d_in[i];
        else if (s == ROWS * 2)        { if (!pxy) pxy = (const float*)d_in[i];
                                         else      pwh = (const float*)d_in[i]; }
        else if (s == ROWS * CC)         cls  = (const float*)d_in[i];
        else if (s == BATCH * MM * CC)   tl   = (const float*)d_in[i];
        else if (s == BATCH * MM * 4)    tobj = (const float*)d_in[i];
    }
    yolo_loss_kernel<<<NBLK, NTHR>>>(conf, pxy, pwh, cls, tl, tobj,
                                     (float*)d_out, out_size);
}

// round 16
// speedup vs baseline: 1.1822x; 1.1822x over previous
#include <cuda_runtime.h>

#define BATCH 128
#define HH 19
#define AA 5
#define CC 81
#define NN 361
#define NAA 1805
#define MM 24
#define ROWS 231040          // BATCH*NAA
#define NBOX (BATCH*MM)      // 3072
#define EPSF 1e-7f

#define NBLK 888             // 148 SMs * 6 blocks (31.1KB smem, <=42 regs)
#define NTHR 256
#define NWPB (NTHR/32)       // 8
#define WROWS 4              // rows per tile
#define WELEM (WROWS*CC)     // 324 floats = 1296 B (16B-divisible)
#define WF4   (WELEM/4)      // 81
#define DEPTH 3              // ring depth: 2 tiles in flight
#define NWT   (ROWS/WROWS)   // 57760 tiles
#define TOTW  (NBLK*NWPB)    // 7104 warps
#define KBASE (NWT/TOTW)     // 8
#define KREM  (NWT%TOTW)     // 928 warps get 9 tiles

// ---- device scratch (zero-init; reset by finishing block each call) ----
__device__ float g_Sce[NAA];
__device__ float g_cnt[NAA];
__device__ float g_corr[NAA];
__device__ float g_acc[8];        // 0 noobj_sub, 1 obj, 2 xy, 3 wh, 4 noobj_total
__device__ unsigned g_done;

__constant__ float c_aw[5] = {0.57273f, 1.87446f, 3.33843f, 7.88282f, 9.77052f};
__constant__ float c_ah[5] = {0.677385f, 2.06253f, 5.47434f, 3.52778f, 9.16828f};

__device__ __forceinline__ void cp16(unsigned s, const void* g) {
    asm volatile("cp.async.cg.shared.global [%0], [%1], 16;\n" :: "r"(s), "l"(g));
}
__device__ __forceinline__ void cpcommit() {
    asm volatile("cp.async.commit_group;\n" ::: "memory");
}
__device__ __forceinline__ void issue_tile(unsigned dstb, const float* cls, int t, int lane) {
    const char* src = (const char*)(cls + (size_t)t * WELEM);
    #pragma unroll
    for (int i = lane; i < WF4; i += 32)
        cp16(dstb + i * 16, src + (size_t)i * 16);
    cpcommit();
}

__global__ void __launch_bounds__(NTHR, 6)
yolo_loss_kernel(const float* __restrict__ conf,
                 const float* __restrict__ pred_xy,
                 const float* __restrict__ pred_wh,
                 const float* __restrict__ cls,
                 const float* __restrict__ tlabel,
                 const float* __restrict__ tobj,
                 float* __restrict__ out, int out_size) {
    __shared__ __align__(16) float sm[NWPB][DEPTH][WELEM];   // 31104 B
    __shared__ float s_no[NWPB];
    __shared__ int   s_last;

    const int tid  = threadIdx.x;
    const int lane = tid & 31;
    const int wid  = tid >> 5;
    const int bx   = blockIdx.x;

    // ====== per-warp run assignment (contiguous 8-9 tiles) ======
    const int gw = bx * NWPB + wid;                           // 0..7103
    const int tbase = (gw < KREM) ? gw * (KBASE + 1)
                                  : KREM * (KBASE + 1) + (gw - KREM) * KBASE;
    const int tcnt  = (gw < KREM) ? (KBASE + 1) : KBASE;      // 9 or 8

    unsigned smb[DEPTH];
    #pragma unroll
    for (int d = 0; d < DEPTH; d++)
        smb[d] = (unsigned)__cvta_generic_to_shared(&sm[wid][d][0]);

    // ====== prologue: issue tiles 0..1 (tcnt >= 8 always) ======
    issue_tile(smb[0], cls, tbase + 0, lane);
    issue_tile(smb[1], cls, tbase + 1, lane);

    // ====== Phase 1: gt assignment, <=1 box per warp, lane-parallel ======
    if (gw < NBOX) {
        const float4 tov = *(const float4*)(tobj + (size_t)gw * 4);
        float gx = tov.x * (1.f/32.f), gy = tov.y * (1.f/32.f);
        float gwd = tov.z * (1.f/32.f), ghd = tov.w * (1.f/32.f);
        int cell = (int)gy * HH + (int)gx;
        int b = gw / MM;
        int base = (b * NN + cell) * AA;

        float bi = -1.f; int best = 0; unsigned overm = 0;
        #pragma unroll
        for (int a = 0; a < 5; a++) {
            float inter = fminf(c_aw[a], gwd) * fminf(c_ah[a], ghd);
            float iou = inter / (c_aw[a] * c_ah[a] + gwd * ghd - inter + EPSF);
            if (iou > 0.6f) overm |= (1u << a);
            if (iou > bi) { bi = iou; best = a; }
        }

        const float* tl = tlabel + (size_t)gw * CC;
        unsigned m0 = __ballot_sync(0xffffffffu, tl[lane] > 0.5f);
        unsigned m1 = __ballot_sync(0xffffffffu, tl[lane + 32] > 0.5f);
        unsigned m2 = __ballot_sync(0xffffffffu, (lane < CC - 64) && (tl[lane + 64] > 0.5f));
        int lab = CC - 1;
        if (m0)      lab = __ffs(m0) - 1;
        else if (m1) lab = 32 + __ffs(m1) - 1;
        else if (m2) lab = 64 + __ffs(m2) - 1;

        if (lane < 5) {
            const int a = lane;
            const bool act = (a == best) || ((overm >> a) & 1u);
            if (act) {
                float ca = fminf(fmaxf(conf[base + a], EPSF), 1.f - EPSF);
                atomicAdd(&g_acc[0], -__logf(1.f - ca));
                const float* crow = cls + (size_t)(base + a) * CC;
                atomicAdd(&g_corr[cell * AA + a], crow[CC - 1] - crow[lab]);
            }
            if (a == best) {
                float pw = pred_wh[(size_t)(base + a) * 2];
                float ph = pred_wh[(size_t)(base + a) * 2 + 1];
                float inter = fminf(pw, gwd) * fminf(ph, ghd);
                float iou_pg = inter / (pw * ph + gwd * ghd - inter + EPSF);
                float sw = 2.f - (gwd * (1.f/19.f)) * (ghd * (1.f/19.f));
                float cp = fminf(fmaxf(conf[base + a], EPSF), 1.f - EPSF);
                float objc = -(iou_pg * __logf(cp) + (1.f - iou_pg) * __logf(1.f - cp));
                float px = pred_xy[(size_t)(base + a) * 2];
                float py = pred_xy[(size_t)(base + a) * 2 + 1];
                float xyc = sw * ((px - gx) * (px - gx) + (py - gy) * (py - gy));
                float whc = sw * ((pw - gwd) * (pw - gwd) + (ph - ghd) * (ph - ghd));
                atomicAdd(&g_cnt[cell * AA + a], 1.f);
                atomicAdd(&g_acc[1], objc);
                atomicAdd(&g_acc[2], xyc);
                atomicAdd(&g_acc[3], whc);
            }
        }
    }

    // ====== conf noobj pass (overlaps in-flight copies) ======
    float nacc = 0.f;
    {
        const float4* c4 = (const float4*)conf;
        for (int i = bx * NTHR + tid; i < ROWS / 4; i += NBLK * NTHR) {
            float4 v = c4[i];
            float p0 = fminf(fmaxf(v.x, EPSF), 1.f - EPSF);
            float p1 = fminf(fmaxf(v.y, EPSF), 1.f - EPSF);
            float p2 = fminf(fmaxf(v.z, EPSF), 1.f - EPSF);
            float p3 = fminf(fmaxf(v.w, EPSF), 1.f - EPSF);
            nacc -= __logf(1.f - p0) + __logf(1.f - p1)
                  + __logf(1.f - p2) + __logf(1.f - p3);
        }
    }

    // ====== Phase 2: depth-3 ring over contiguous run ======
    const int r = lane >> 3;              // 0..3 (row within tile)
    const int q = lane & 7;               // 8 lanes per row
    const int start = (q == 0) ? 0 : (10 * q + 1);    // 0,11,21,...,71

    int n0 = (tbase * WROWS) % NAA;       // row index mod NAA; +4 per tile

    for (int j = 0; j < tcnt; j++) {
        if (j + 2 < tcnt) {
            issue_tile(smb[(j + 2) % DEPTH], cls, tbase + j + 2, lane);
            asm volatile("cp.async.wait_group 2;\n" ::: "memory");
        } else if (j + 1 < tcnt) {
            asm volatile("cp.async.wait_group 1;\n" ::: "memory");
        } else {
            asm volatile("cp.async.wait_group 0;\n" ::: "memory");
        }
        __syncwarp();

        {
            const float* rp = &sm[wid][j % DEPTH][r * CC + start];
            float a0 = 0.f, a1 = 0.f;
            #pragma unroll
            for (int i = 0; i < 10; i += 2) {
                a0 += __expf(rp[i]);
                a1 += __expf(rp[i + 1]);
            }
            float x80 = rp[9];                     // q==7: 71+9 = 80
            if (q == 0) a0 += __expf(rp[10]);
            float s = a0 + a1;
            s += __shfl_xor_sync(0xffffffffu, s, 1);
            s += __shfl_xor_sync(0xffffffffu, s, 2);
            s += __shfl_xor_sync(0xffffffffu, s, 4);
            if (q == 7) {
                int idx = n0 + r;
                if (idx >= NAA) idx -= NAA;
                atomicAdd(&g_Sce[idx], __logf(s) - x80);
            }
        }
        __syncwarp();                     // all lanes done before slot reuse
        n0 += WROWS;
        if (n0 >= NAA) n0 -= NAA;
    }

    // ====== block-reduce noobj partial, then last-block combine ======
    #pragma unroll
    for (int o = 16; o > 0; o >>= 1)
        nacc += __shfl_xor_sync(0xffffffffu, nacc, o);
    if (lane == 0) s_no[wid] = nacc;
    __syncthreads();
    if (tid == 0) {
        float tn = 0.f;
        #pragma unroll
        for (int i = 0; i < NWPB; i++) tn += s_no[i];
        atomicAdd(&g_acc[4], tn);
        __threadfence();
        unsigned d = atomicAdd(&g_done, 1u);
        s_last = (d == (unsigned)(gridDim.x - 1)) ? 1 : 0;
    }
    __syncthreads();

    if (s_last) {
        __threadfence();
        float* red = &sm[0][0][0];
        float p = 0.f;
        for (int n = tid; n < NAA; n += NTHR)
            p += g_cnt[n] * (g_Sce[n] + g_corr[n]);
        red[tid] = p;
        __syncthreads();
        for (int s2 = NTHR / 2; s2 > 0; s2 >>= 1) {
            if (tid < s2) red[tid] += red[tid + s2];
            __syncthreads();
        }
        if (tid == 0) {
            const float invB = 1.f / (float)BATCH;
            float noobj = (g_acc[4] - g_acc[0]) * invB;   // SCALE_NOOBJ = 1
            float obj   = 5.f * g_acc[1] * invB;
            float xy    = 5.f * g_acc[2] * invB;
            float wh    = 5.f * g_acc[3] * invB;
            float score = 5.f * red[0] * invB;
            float total = noobj + obj + xy + wh + score;
            out[0] = total;
            if (out_size >= 6) {
                out[1] = noobj; out[2] = obj; out[3] = score; out[4] = xy; out[5] = wh;
            }
        }
        __syncthreads();
        for (int n = tid; n < NAA; n += NTHR) {
            g_Sce[n] = 0.f; g_cnt[n] = 0.f; g_corr[n] = 0.f;
        }
        if (tid < 8) g_acc[tid] = 0.f;
        if (tid == 0) g_done = 0u;
        __threadfence();
    }
}

extern "C" void kernel_launch(void* const* d_in, const int* in_sizes, int n_in,
                              void* d_out, int out_size) {
    const float *conf = nullptr, *pxy = nullptr, *pwh = nullptr;
    const float *cls = nullptr, *tl = nullptr, *tobj = nullptr;
    for (int i = 0; i < n_in; i++) {
        int s = in_sizes[i];
        if (s == ROWS)                   conf = (const float*)d_in[i];
        else if (s == ROWS * 2)        { if (!pxy) pxy = (const float*)d_in[i];
                                         else      pwh = (const float*)d_in[i]; }
        else if (s == ROWS * CC)         cls  = (const float*)d_in[i];
        else if (s == BATCH * MM * CC)   tl   = (const float*)d_in[i];
        else if (s == BATCH * MM * 4)    tobj = (const float*)d_in[i];
    }
    yolo_loss_kernel<<<NBLK, NTHR>>>(conf, pxy, pwh, cls, tl, tobj,
                                     (float*)d_out, out_size);
}